// round 2
// baseline (speedup 1.0000x reference)
#include <cuda_runtime.h>
#include <math_constants.h>

#define S_LEN 2048
#define NBATCH 4
#define EMB 1024
#define NH 16
#define HD 64

// Scratch (allocation-free rule: __device__ globals)
__device__ float g_q[NBATCH * S_LEN * EMB];
__device__ float g_k[NBATCH * S_LEN * EMB];
__device__ float g_v[NBATCH * S_LEN * EMB];
__device__ float g_att[NBATCH * S_LEN * EMB];

// ---------------------------------------------------------------------------
// GEMM: C[M,1024] = A[M,1024] @ B[1024,1024] + bias, all row-major fp32
// 128x128 block tile, BK=16, 256 threads, 8x8 per thread, double-buffered smem
// ---------------------------------------------------------------------------
#define BM 128
#define BN 128
#define BKG 16

__global__ __launch_bounds__(256, 2)
void gemm_bias(const float* __restrict__ A, const float* __restrict__ B,
               const float* __restrict__ bias, float* __restrict__ C, int M)
{
    const int N = EMB, K = EMB;
    __shared__ float As[2][BKG][BM + 4];   // transposed A tile, padded
    __shared__ float Bs[2][BKG][BN];

    const int tid = threadIdx.x;
    const int tx = tid & 15;
    const int ty = tid >> 4;
    const int m0 = blockIdx.y * BM;
    const int n0 = blockIdx.x * BN;

    const int arow = tid >> 2;          // 0..63 (+64 for u=1)
    const int ac4  = tid & 3;           // float4 col within BK=16
    const int brow = tid >> 5;          // 0..7 (+8 for u=1)
    const int bc4  = tid & 31;          // float4 col within BN=128

    float4 ra[2], rb[2];

    // prefetch k-tile 0
#pragma unroll
    for (int u = 0; u < 2; u++) {
        ra[u] = *(const float4*)(A + (size_t)(m0 + arow + u * 64) * K + ac4 * 4);
        rb[u] = *(const float4*)(B + (size_t)(brow + u * 8) * N + n0 + bc4 * 4);
    }
#pragma unroll
    for (int u = 0; u < 2; u++) {
        As[0][ac4 * 4 + 0][arow + u * 64] = ra[u].x;
        As[0][ac4 * 4 + 1][arow + u * 64] = ra[u].y;
        As[0][ac4 * 4 + 2][arow + u * 64] = ra[u].z;
        As[0][ac4 * 4 + 3][arow + u * 64] = ra[u].w;
        *(float4*)&Bs[0][brow + u * 8][bc4 * 4] = rb[u];
    }
    __syncthreads();

    float acc[8][8] = {};
    const int nk = K / BKG;   // 64
    int buf = 0;

    for (int kt = 0; kt < nk; kt++) {
        if (kt + 1 < nk) {
#pragma unroll
            for (int u = 0; u < 2; u++) {
                ra[u] = *(const float4*)(A + (size_t)(m0 + arow + u * 64) * K
                                         + (kt + 1) * BKG + ac4 * 4);
                rb[u] = *(const float4*)(B + (size_t)((kt + 1) * BKG + brow + u * 8) * N
                                         + n0 + bc4 * 4);
            }
        }
#pragma unroll
        for (int kk = 0; kk < BKG; kk++) {
            float4 a0 = *(const float4*)&As[buf][kk][ty * 8];
            float4 a1 = *(const float4*)&As[buf][kk][ty * 8 + 4];
            float4 b0 = *(const float4*)&Bs[buf][kk][tx * 8];
            float4 b1 = *(const float4*)&Bs[buf][kk][tx * 8 + 4];
            float av[8] = {a0.x, a0.y, a0.z, a0.w, a1.x, a1.y, a1.z, a1.w};
            float bv[8] = {b0.x, b0.y, b0.z, b0.w, b1.x, b1.y, b1.z, b1.w};
#pragma unroll
            for (int i = 0; i < 8; i++)
#pragma unroll
                for (int j = 0; j < 8; j++)
                    acc[i][j] += av[i] * bv[j];
        }
        if (kt + 1 < nk) {
            __syncthreads();
#pragma unroll
            for (int u = 0; u < 2; u++) {
                As[buf ^ 1][ac4 * 4 + 0][arow + u * 64] = ra[u].x;
                As[buf ^ 1][ac4 * 4 + 1][arow + u * 64] = ra[u].y;
                As[buf ^ 1][ac4 * 4 + 2][arow + u * 64] = ra[u].z;
                As[buf ^ 1][ac4 * 4 + 3][arow + u * 64] = ra[u].w;
                *(float4*)&Bs[buf ^ 1][brow + u * 8][bc4 * 4] = rb[u];
            }
            __syncthreads();
            buf ^= 1;
        }
    }

#pragma unroll
    for (int i = 0; i < 8; i++) {
        const size_t row = (size_t)(m0 + ty * 8 + i);
#pragma unroll
        for (int j4 = 0; j4 < 2; j4++) {
            const int col = n0 + tx * 8 + j4 * 4;
            float4 bs = *(const float4*)(bias + col);
            float4 o;
            o.x = acc[i][j4 * 4 + 0] + bs.x;
            o.y = acc[i][j4 * 4 + 1] + bs.y;
            o.z = acc[i][j4 * 4 + 2] + bs.z;
            o.w = acc[i][j4 * 4 + 3] + bs.w;
            *(float4*)(C + row * N + col) = o;
        }
    }
}

// ---------------------------------------------------------------------------
// Flash attention, fp32. One block = one (batch, head, 64-row Q tile).
// 256 threads (16x16), each owns a 4x4 fragment. Online softmax with
// 16-lane shuffle row reductions. Scores staged through smem (K buffer reuse)
// for the P@V product.
// ---------------------------------------------------------------------------
#define BQ 64
#define BKT 64
#define DP 68   // padded row stride (floats), multiple of 4

__global__ __launch_bounds__(256)
void attn_kernel(const float* __restrict__ Q, const float* __restrict__ Kt,
                 const float* __restrict__ V, const int* __restrict__ mask,
                 float* __restrict__ Out)
{
    extern __shared__ float sm[];
    float (*Qs)[DP]  = (float(*)[DP])sm;              // Q^T : [d][m]
    float (*KPs)[DP] = (float(*)[DP])(sm + HD * DP);  // K^T : [d][n], reused as P[m][k]
    float (*Vs)[DP]  = (float(*)[DP])(sm + 2 * HD * DP); // V : [k][d]

    const int tid = threadIdx.x;
    const int tx = tid & 15;
    const int ty = tid >> 4;
    const int qb = blockIdx.x;
    const int h  = blockIdx.y;
    const int n  = blockIdx.z;

    const int q0 = qb * BQ;
    const size_t base = ((size_t)n * S_LEN) * EMB + (size_t)h * HD;

    // Load Q tile transposed, pre-scaled by 1/sqrt(E) = 1/32
    {
        const int tok = tid >> 2;
        const int d0 = (tid & 3) * 16;
        const float* src = Q + base + (size_t)(q0 + tok) * EMB + d0;
#pragma unroll
        for (int u = 0; u < 4; u++) {
            float4 v = *(const float4*)(src + u * 4);
            Qs[d0 + u * 4 + 0][tok] = v.x * 0.03125f;
            Qs[d0 + u * 4 + 1][tok] = v.y * 0.03125f;
            Qs[d0 + u * 4 + 2][tok] = v.z * 0.03125f;
            Qs[d0 + u * 4 + 3][tok] = v.w * 0.03125f;
        }
    }

    float o[4][4] = {};
    float mrow[4], lrow[4];
#pragma unroll
    for (int i = 0; i < 4; i++) { mrow[i] = -3.0e38f; lrow[i] = 0.0f; }

    for (int kt = 0; kt < S_LEN / BKT; kt++) {
        const int k0 = kt * BKT;
        __syncthreads();   // previous iteration done reading KPs/Vs
        {
            const int tok = tid >> 2;
            const int d0 = (tid & 3) * 16;
            const float* ksrc = Kt + base + (size_t)(k0 + tok) * EMB + d0;
            const float* vsrc = V  + base + (size_t)(k0 + tok) * EMB + d0;
#pragma unroll
            for (int u = 0; u < 4; u++) {
                float4 kv = *(const float4*)(ksrc + u * 4);
                KPs[d0 + u * 4 + 0][tok] = kv.x;
                KPs[d0 + u * 4 + 1][tok] = kv.y;
                KPs[d0 + u * 4 + 2][tok] = kv.z;
                KPs[d0 + u * 4 + 3][tok] = kv.w;
                *(float4*)&Vs[tok][d0 + u * 4] = *(const float4*)(vsrc + u * 4);
            }
        }
        __syncthreads();

        // S = (Q/32) @ K^T : 4x4 fragment per thread
        float s[4][4] = {};
#pragma unroll 8
        for (int d = 0; d < HD; d++) {
            float4 a = *(const float4*)&Qs[d][ty * 4];
            float4 b = *(const float4*)&KPs[d][tx * 4];
            float av[4] = {a.x, a.y, a.z, a.w};
            float bv[4] = {b.x, b.y, b.z, b.w};
#pragma unroll
            for (int i = 0; i < 4; i++)
#pragma unroll
                for (int j = 0; j < 4; j++)
                    s[i][j] += av[i] * bv[j];
        }

        // mask (mask shape [N,1,1,S]: per key position)
        {
            const int* mp = mask + n * S_LEN + k0 + tx * 4;
#pragma unroll
            for (int j = 0; j < 4; j++) {
                if (mp[j] == 0) {
                    s[0][j] = -1e20f; s[1][j] = -1e20f;
                    s[2][j] = -1e20f; s[3][j] = -1e20f;
                }
            }
        }

        // online softmax; rows of the fragment span 16 lanes (same ty)
        float p[4][4];
#pragma unroll
        for (int i = 0; i < 4; i++) {
            float rm = fmaxf(fmaxf(s[i][0], s[i][1]), fmaxf(s[i][2], s[i][3]));
#pragma unroll
            for (int off = 8; off >= 1; off >>= 1)
                rm = fmaxf(rm, __shfl_xor_sync(0xffffffffu, rm, off, 16));
            const float mnew = fmaxf(mrow[i], rm);
            const float corr = __expf(mrow[i] - mnew);
            mrow[i] = mnew;
            float ls = 0.0f;
#pragma unroll
            for (int j = 0; j < 4; j++) {
                p[i][j] = __expf(s[i][j] - mnew);
                ls += p[i][j];
            }
#pragma unroll
            for (int off = 8; off >= 1; off >>= 1)
                ls += __shfl_xor_sync(0xffffffffu, ls, off, 16);
            lrow[i] = lrow[i] * corr + ls;
#pragma unroll
            for (int j = 0; j < 4; j++) o[i][j] *= corr;
        }

        __syncthreads();   // all threads done reading KPs as K
        // stage P into smem (reuse K buffer): P[m][k]
#pragma unroll
        for (int i = 0; i < 4; i++)
#pragma unroll
            for (int j = 0; j < 4; j++)
                KPs[ty * 4 + i][tx * 4 + j] = p[i][j];
        __syncthreads();

        // O += P @ V
#pragma unroll 8
        for (int k = 0; k < BKT; k++) {
            float4 vv = *(const float4*)&Vs[k][tx * 4];
#pragma unroll
            for (int i = 0; i < 4; i++) {
                const float pv = KPs[ty * 4 + i][k];
                o[i][0] += pv * vv.x;
                o[i][1] += pv * vv.y;
                o[i][2] += pv * vv.z;
                o[i][3] += pv * vv.w;
            }
        }
    }

    // normalize + write
#pragma unroll
    for (int i = 0; i < 4; i++) {
        const float inv = 1.0f / lrow[i];
        float4 ov = make_float4(o[i][0] * inv, o[i][1] * inv,
                                o[i][2] * inv, o[i][3] * inv);
        *(float4*)(Out + base + (size_t)(q0 + ty * 4 + i) * EMB + tx * 4) = ov;
    }
}

// ---------------------------------------------------------------------------
extern "C" void kernel_launch(void* const* d_in, const int* in_sizes, int n_in,
                              void* d_out, int out_size)
{
    const float* values = (const float*)d_in[0];
    const float* keys   = (const float*)d_in[1];
    const float* query  = (const float*)d_in[2];
    const int*   mask   = (const int*)  d_in[3];
    const float* Wv = (const float*)d_in[4];
    const float* bv = (const float*)d_in[5];
    const float* Wk = (const float*)d_in[6];
    const float* bk = (const float*)d_in[7];
    const float* Wq = (const float*)d_in[8];
    const float* bq = (const float*)d_in[9];
    const float* Wo = (const float*)d_in[10];
    const float* bo = (const float*)d_in[11];
    float* out = (float*)d_out;

    float *q, *k, *v, *att;
    cudaGetSymbolAddress((void**)&q,   g_q);
    cudaGetSymbolAddress((void**)&k,   g_k);
    cudaGetSymbolAddress((void**)&v,   g_v);
    cudaGetSymbolAddress((void**)&att, g_att);

    const int M = NBATCH * S_LEN;           // 8192
    const int attn_smem = 3 * HD * DP * (int)sizeof(float);  // 52224 B
    cudaFuncSetAttribute(attn_kernel,
                         cudaFuncAttributeMaxDynamicSharedMemorySize, attn_smem);

    dim3 ggrid(EMB / BN, M / BM);           // (8, 64)
    gemm_bias<<<ggrid, 256>>>(query,  Wq, bq, q, M);
    gemm_bias<<<ggrid, 256>>>(keys,   Wk, bk, k, M);
    gemm_bias<<<ggrid, 256>>>(values, Wv, bv, v, M);

    dim3 agrid(S_LEN / BQ, NH, NBATCH);     // (32, 16, 4)
    attn_kernel<<<agrid, 256, attn_smem>>>(q, k, v, mask, att);

    gemm_bias<<<ggrid, 256>>>(att, Wo, bo, out, M);
}

// round 4
// speedup vs baseline: 1.2855x; 1.2855x over previous
#include <cuda_runtime.h>
#include <cuda_bf16.h>
#include <cstdint>

#define S_LEN 2048
#define NBATCH 4
#define EMB 1024
#define NH 16
#define HD 64

// ---------------------------------------------------------------------------
// Scratch (allocation-free rule: __device__ globals)
// ---------------------------------------------------------------------------
__device__ float g_q[NBATCH * S_LEN * EMB];
__device__ float g_k[NBATCH * S_LEN * EMB];
__device__ float g_v[NBATCH * S_LEN * EMB];
__device__ float g_att[NBATCH * S_LEN * EMB];
__device__ __nv_bfloat16 g_wt_hi[4 * EMB * EMB];   // W^T split high, [4][N][K]
__device__ __nv_bfloat16 g_wt_lo[4 * EMB * EMB];   // W^T split low
__device__ __nv_bfloat16 g_a_hi[NBATCH * S_LEN * EMB];  // activation split high
__device__ __nv_bfloat16 g_a_lo[NBATCH * S_LEN * EMB];  // activation split low

// ---------------------------------------------------------------------------
// Base-ISA PTX helpers (no tcgen05 — harness PTX target is plain sm_103)
// ---------------------------------------------------------------------------
__device__ __forceinline__ uint32_t smem_to_u32(const void* p) {
    uint32_t a;
    asm("{ .reg .u64 t; cvta.to.shared.u64 t, %1; cvt.u32.u64 %0, t; }"
        : "=r"(a) : "l"(p));
    return a;
}

__device__ __forceinline__ void ldsm_x4(uint32_t* r, uint32_t addr) {
    asm volatile("ldmatrix.sync.aligned.m8n8.x4.shared.b16 {%0,%1,%2,%3}, [%4];"
                 : "=r"(r[0]), "=r"(r[1]), "=r"(r[2]), "=r"(r[3]) : "r"(addr));
}

__device__ __forceinline__ void mma_bf16(float* d, const uint32_t* a,
                                         uint32_t b0, uint32_t b1) {
    asm volatile(
        "mma.sync.aligned.m16n8k16.row.col.f32.bf16.bf16.f32 "
        "{%0,%1,%2,%3}, {%4,%5,%6,%7}, {%8,%9}, {%0,%1,%2,%3};"
        : "+f"(d[0]), "+f"(d[1]), "+f"(d[2]), "+f"(d[3])
        : "r"(a[0]), "r"(a[1]), "r"(a[2]), "r"(a[3]), "r"(b0), "r"(b1));
}

__device__ __forceinline__ void cp16(uint32_t s, const void* g) {
    asm volatile("cp.async.cg.shared.global [%0], [%1], 16;" :: "r"(s), "l"(g));
}
__device__ __forceinline__ void cp_commit() {
    asm volatile("cp.async.commit_group;" ::: "memory");
}
template <int N>
__device__ __forceinline__ void cp_wait() {
    asm volatile("cp.async.wait_group %0;" :: "n"(N) : "memory");
}

// ---------------------------------------------------------------------------
// Weight transpose + split: W[K][N] fp32 -> Wt_hi/Wt_lo[N][K] bf16
// ---------------------------------------------------------------------------
__global__ void transpose_split(const float* __restrict__ W,
                                __nv_bfloat16* __restrict__ Th,
                                __nv_bfloat16* __restrict__ Tl)
{
    __shared__ float t[32][33];
    const int tx = threadIdx.x, ty = threadIdx.y;
    const int bx = blockIdx.x * 32, by = blockIdx.y * 32;
#pragma unroll
    for (int j = 0; j < 4; j++)
        t[ty + j * 8][tx] = W[(size_t)(by + ty + j * 8) * EMB + bx + tx];
    __syncthreads();
#pragma unroll
    for (int j = 0; j < 4; j++) {
        float v = t[tx][ty + j * 8];
        __nv_bfloat16 hi = __float2bfloat16_rn(v);
        __nv_bfloat16 lo = __float2bfloat16_rn(v - __bfloat162float(hi));
        const size_t o = (size_t)(bx + ty + j * 8) * EMB + by + tx;
        Th[o] = hi;
        Tl[o] = lo;
    }
}

// ---------------------------------------------------------------------------
// Activation split: X fp32 -> hi/lo bf16 (elementwise)
// ---------------------------------------------------------------------------
union B4 { __nv_bfloat16 b[4]; uint2 u; };

__global__ __launch_bounds__(256)
void split2(const float* __restrict__ X, __nv_bfloat16* __restrict__ H,
            __nv_bfloat16* __restrict__ L)
{
    const int i = blockIdx.x * 256 + threadIdx.x;   // float4 index
    float4 v = ((const float4*)X)[i];
    float f[4] = {v.x, v.y, v.z, v.w};
    B4 h, l;
#pragma unroll
    for (int j = 0; j < 4; j++) {
        h.b[j] = __float2bfloat16_rn(f[j]);
        l.b[j] = __float2bfloat16_rn(f[j] - __bfloat162float(h.b[j]));
    }
    ((uint2*)H)[i] = h.u;
    ((uint2*)L)[i] = l.u;
}

// ---------------------------------------------------------------------------
// mma.sync split-bf16 GEMM: C[M,1024] = A @ W + bias  (fp32-accurate)
// A pre-split hi/lo [M][K] bf16, W pre-transposed+split [N][K] bf16.
// 128x128 block, BK=32, 8 warps (64x32 each), cp.async double buffer.
// ---------------------------------------------------------------------------
#define LDT 40                       // smem row stride (bf16 elems), conflict-free
#define TBY (128 * LDT * 2)          // one tile: 10240 bytes
#define BUFB (4 * TBY)               // Ahi|Alo|Bhi|Blo per buffer

__global__ __launch_bounds__(256, 2)
void gemm_ms(const __nv_bfloat16* __restrict__ Ahi,
             const __nv_bfloat16* __restrict__ Alo,
             const __nv_bfloat16* __restrict__ Bhi,
             const __nv_bfloat16* __restrict__ Blo,
             const float* __restrict__ bias, float* __restrict__ C)
{
    extern __shared__ char smc[];
    const uint32_t sb = smem_to_u32(smc);
    const int tid = threadIdx.x;
    const int wid = tid >> 5, lane = tid & 31;
    const int m0 = blockIdx.y * 128, n0 = blockIdx.x * 128;

    // ---- async load helper data: chunk c in [0,512): row=c>>2, c4=c&3 ----
    const __nv_bfloat16* gp[4] = {Ahi, Alo, Bhi, Blo};
    const int gbase[4] = {m0, m0, n0, n0};

    // ---- ldmatrix lane offset ----
    const int lrow = (lane & 7) + ((lane >> 3) & 1) * 8;
    const int lcol = (lane >> 4) * 8;
    const uint32_t laneoff = (uint32_t)(lrow * (LDT * 2) + lcol * 2);

    const int wm = (wid & 1) * 64;
    const int wn = (wid >> 1) * 32;

    float acc[4][4][4];
#pragma unroll
    for (int i = 0; i < 4; i++)
#pragma unroll
        for (int j = 0; j < 4; j++)
#pragma unroll
            for (int e = 0; e < 4; e++) acc[i][j][e] = 0.0f;

    // ---- prologue: issue buffer 0 (kc = 0) ----
#pragma unroll
    for (int arr = 0; arr < 4; arr++) {
#pragma unroll
        for (int h = 0; h < 2; h++) {
            const int c = tid + h * 256;
            const int row = c >> 2, c4 = c & 3;
            cp16(sb + arr * TBY + row * (LDT * 2) + c4 * 16,
                 gp[arr] + (size_t)(gbase[arr] + row) * EMB + c4 * 8);
        }
    }
    cp_commit();

    const int NKC = EMB / 32;   // 32
    for (int kc = 0; kc < NKC; kc++) {
        const int buf = kc & 1;
        // issue next buffer
        if (kc + 1 < NKC) {
            const uint32_t so = sb + (buf ^ 1) * BUFB;
            const int koff = (kc + 1) * 32;
#pragma unroll
            for (int arr = 0; arr < 4; arr++) {
#pragma unroll
                for (int h = 0; h < 2; h++) {
                    const int c = tid + h * 256;
                    const int row = c >> 2, c4 = c & 3;
                    cp16(so + arr * TBY + row * (LDT * 2) + c4 * 16,
                         gp[arr] + (size_t)(gbase[arr] + row) * EMB + koff + c4 * 8);
                }
            }
            cp_commit();
            cp_wait<1>();
        } else {
            cp_wait<0>();
        }
        __syncthreads();

        const uint32_t tb = sb + buf * BUFB;
#pragma unroll
        for (int ks = 0; ks < 32; ks += 16) {
            uint32_t ah[4][4], al[4][4];
#pragma unroll
            for (int i = 0; i < 4; i++) {
                const uint32_t ao = tb + (wm + i * 16) * (LDT * 2) + ks * 2 + laneoff;
                ldsm_x4(ah[i], ao);
                ldsm_x4(al[i], ao + TBY);
            }
            uint32_t b0[4], b1[4];
            {
                const uint32_t bo = tb + 2 * TBY + wn * (LDT * 2) + ks * 2 + laneoff;
                ldsm_x4(b0, bo);
                ldsm_x4(b1, bo + 16 * (LDT * 2));
            }
            // products: Ahi*Bhi and Alo*Bhi
#pragma unroll
            for (int i = 0; i < 4; i++) {
                mma_bf16(acc[i][0], ah[i], b0[0], b0[2]);
                mma_bf16(acc[i][1], ah[i], b0[1], b0[3]);
                mma_bf16(acc[i][2], ah[i], b1[0], b1[2]);
                mma_bf16(acc[i][3], ah[i], b1[1], b1[3]);
            }
#pragma unroll
            for (int i = 0; i < 4; i++) {
                mma_bf16(acc[i][0], al[i], b0[0], b0[2]);
                mma_bf16(acc[i][1], al[i], b0[1], b0[3]);
                mma_bf16(acc[i][2], al[i], b1[0], b1[2]);
                mma_bf16(acc[i][3], al[i], b1[1], b1[3]);
            }
            // reload B as lo, product Ahi*Blo
            {
                const uint32_t bo = tb + 3 * TBY + wn * (LDT * 2) + ks * 2 + laneoff;
                ldsm_x4(b0, bo);
                ldsm_x4(b1, bo + 16 * (LDT * 2));
            }
#pragma unroll
            for (int i = 0; i < 4; i++) {
                mma_bf16(acc[i][0], ah[i], b0[0], b0[2]);
                mma_bf16(acc[i][1], ah[i], b0[1], b0[3]);
                mma_bf16(acc[i][2], ah[i], b1[0], b1[2]);
                mma_bf16(acc[i][3], ah[i], b1[1], b1[3]);
            }
        }
        __syncthreads();
    }

    // ---- epilogue: bias + store ----
#pragma unroll
    for (int i = 0; i < 4; i++) {
        const int r = m0 + wm + i * 16 + (lane >> 2);
#pragma unroll
        for (int j = 0; j < 4; j++) {
            const int c = n0 + wn + j * 8 + (lane & 3) * 2;
            const float2 bv = *(const float2*)(bias + c);
            float2 o0, o1;
            o0.x = acc[i][j][0] + bv.x;
            o0.y = acc[i][j][1] + bv.y;
            o1.x = acc[i][j][2] + bv.x;
            o1.y = acc[i][j][3] + bv.y;
            *(float2*)(C + (size_t)r * EMB + c) = o0;
            *(float2*)(C + (size_t)(r + 8) * EMB + c) = o1;
        }
    }
}

// ---------------------------------------------------------------------------
// Flash attention, fp32 (unchanged — proven correct, round-2)
// ---------------------------------------------------------------------------
#define BQ 64
#define BKT 64
#define DP 68

__global__ __launch_bounds__(256)
void attn_kernel(const float* __restrict__ Q, const float* __restrict__ Kt,
                 const float* __restrict__ V, const int* __restrict__ mask,
                 float* __restrict__ Out)
{
    extern __shared__ float sm[];
    float (*Qs)[DP]  = (float(*)[DP])sm;
    float (*KPs)[DP] = (float(*)[DP])(sm + HD * DP);
    float (*Vs)[DP]  = (float(*)[DP])(sm + 2 * HD * DP);

    const int tid = threadIdx.x;
    const int tx = tid & 15;
    const int ty = tid >> 4;
    const int qb = blockIdx.x;
    const int h  = blockIdx.y;
    const int n  = blockIdx.z;

    const int q0 = qb * BQ;
    const size_t base = ((size_t)n * S_LEN) * EMB + (size_t)h * HD;

    {
        const int tok = tid >> 2;
        const int d0 = (tid & 3) * 16;
        const float* src = Q + base + (size_t)(q0 + tok) * EMB + d0;
#pragma unroll
        for (int u = 0; u < 4; u++) {
            float4 v = *(const float4*)(src + u * 4);
            Qs[d0 + u * 4 + 0][tok] = v.x * 0.03125f;
            Qs[d0 + u * 4 + 1][tok] = v.y * 0.03125f;
            Qs[d0 + u * 4 + 2][tok] = v.z * 0.03125f;
            Qs[d0 + u * 4 + 3][tok] = v.w * 0.03125f;
        }
    }

    float o[4][4] = {};
    float mrow[4], lrow[4];
#pragma unroll
    for (int i = 0; i < 4; i++) { mrow[i] = -3.0e38f; lrow[i] = 0.0f; }

    for (int kt = 0; kt < S_LEN / BKT; kt++) {
        const int k0 = kt * BKT;
        __syncthreads();
        {
            const int tok = tid >> 2;
            const int d0 = (tid & 3) * 16;
            const float* ksrc = Kt + base + (size_t)(k0 + tok) * EMB + d0;
            const float* vsrc = V  + base + (size_t)(k0 + tok) * EMB + d0;
#pragma unroll
            for (int u = 0; u < 4; u++) {
                float4 kv = *(const float4*)(ksrc + u * 4);
                KPs[d0 + u * 4 + 0][tok] = kv.x;
                KPs[d0 + u * 4 + 1][tok] = kv.y;
                KPs[d0 + u * 4 + 2][tok] = kv.z;
                KPs[d0 + u * 4 + 3][tok] = kv.w;
                *(float4*)&Vs[tok][d0 + u * 4] = *(const float4*)(vsrc + u * 4);
            }
        }
        __syncthreads();

        float s[4][4] = {};
#pragma unroll 8
        for (int d = 0; d < HD; d++) {
            float4 a = *(const float4*)&Qs[d][ty * 4];
            float4 b = *(const float4*)&KPs[d][tx * 4];
            float av[4] = {a.x, a.y, a.z, a.w};
            float bv[4] = {b.x, b.y, b.z, b.w};
#pragma unroll
            for (int i = 0; i < 4; i++)
#pragma unroll
                for (int j = 0; j < 4; j++)
                    s[i][j] += av[i] * bv[j];
        }

        {
            const int* mp = mask + n * S_LEN + k0 + tx * 4;
#pragma unroll
            for (int j = 0; j < 4; j++) {
                if (mp[j] == 0) {
                    s[0][j] = -1e20f; s[1][j] = -1e20f;
                    s[2][j] = -1e20f; s[3][j] = -1e20f;
                }
            }
        }

        float p[4][4];
#pragma unroll
        for (int i = 0; i < 4; i++) {
            float rm = fmaxf(fmaxf(s[i][0], s[i][1]), fmaxf(s[i][2], s[i][3]));
#pragma unroll
            for (int off = 8; off >= 1; off >>= 1)
                rm = fmaxf(rm, __shfl_xor_sync(0xffffffffu, rm, off, 16));
            const float mnew = fmaxf(mrow[i], rm);
            const float corr = __expf(mrow[i] - mnew);
            mrow[i] = mnew;
            float ls = 0.0f;
#pragma unroll
            for (int j = 0; j < 4; j++) {
                p[i][j] = __expf(s[i][j] - mnew);
                ls += p[i][j];
            }
#pragma unroll
            for (int off = 8; off >= 1; off >>= 1)
                ls += __shfl_xor_sync(0xffffffffu, ls, off, 16);
            lrow[i] = lrow[i] * corr + ls;
#pragma unroll
            for (int j = 0; j < 4; j++) o[i][j] *= corr;
        }

        __syncthreads();
#pragma unroll
        for (int i = 0; i < 4; i++)
#pragma unroll
            for (int j = 0; j < 4; j++)
                KPs[ty * 4 + i][tx * 4 + j] = p[i][j];
        __syncthreads();

#pragma unroll 8
        for (int k = 0; k < BKT; k++) {
            float4 vv = *(const float4*)&Vs[k][tx * 4];
#pragma unroll
            for (int i = 0; i < 4; i++) {
                const float pv = KPs[ty * 4 + i][k];
                o[i][0] += pv * vv.x;
                o[i][1] += pv * vv.y;
                o[i][2] += pv * vv.z;
                o[i][3] += pv * vv.w;
            }
        }
    }

#pragma unroll
    for (int i = 0; i < 4; i++) {
        const float inv = 1.0f / lrow[i];
        float4 ov = make_float4(o[i][0] * inv, o[i][1] * inv,
                                o[i][2] * inv, o[i][3] * inv);
        *(float4*)(Out + base + (size_t)(q0 + ty * 4 + i) * EMB + tx * 4) = ov;
    }
}

// ---------------------------------------------------------------------------
extern "C" void kernel_launch(void* const* d_in, const int* in_sizes, int n_in,
                              void* d_out, int out_size)
{
    const float* values = (const float*)d_in[0];
    const float* keys   = (const float*)d_in[1];
    const float* query  = (const float*)d_in[2];
    const int*   mask   = (const int*)  d_in[3];
    const float* Wv = (const float*)d_in[4];
    const float* bv = (const float*)d_in[5];
    const float* Wk = (const float*)d_in[6];
    const float* bk = (const float*)d_in[7];
    const float* Wq = (const float*)d_in[8];
    const float* bq = (const float*)d_in[9];
    const float* Wo = (const float*)d_in[10];
    const float* bo = (const float*)d_in[11];
    float* out = (float*)d_out;

    float *q, *k, *v, *att;
    __nv_bfloat16 *wth, *wtl, *ahi, *alo;
    cudaGetSymbolAddress((void**)&q,   g_q);
    cudaGetSymbolAddress((void**)&k,   g_k);
    cudaGetSymbolAddress((void**)&v,   g_v);
    cudaGetSymbolAddress((void**)&att, g_att);
    cudaGetSymbolAddress((void**)&wth, g_wt_hi);
    cudaGetSymbolAddress((void**)&wtl, g_wt_lo);
    cudaGetSymbolAddress((void**)&ahi, g_a_hi);
    cudaGetSymbolAddress((void**)&alo, g_a_lo);

    const int gemm_smem = 2 * BUFB;                          // 81920 B
    cudaFuncSetAttribute(gemm_ms,
                         cudaFuncAttributeMaxDynamicSharedMemorySize, gemm_smem);
    const int attn_smem = 3 * HD * DP * (int)sizeof(float);  // 52224 B
    cudaFuncSetAttribute(attn_kernel,
                         cudaFuncAttributeMaxDynamicSharedMemorySize, attn_smem);

    const size_t WSZ = (size_t)EMB * EMB;
    const int M = NBATCH * S_LEN;                            // 8192
    dim3 tgrid(32, 32), tblk(32, 8);
    transpose_split<<<tgrid, tblk>>>(Wq, wth + 0 * WSZ, wtl + 0 * WSZ);
    transpose_split<<<tgrid, tblk>>>(Wk, wth + 1 * WSZ, wtl + 1 * WSZ);
    transpose_split<<<tgrid, tblk>>>(Wv, wth + 2 * WSZ, wtl + 2 * WSZ);
    transpose_split<<<tgrid, tblk>>>(Wo, wth + 3 * WSZ, wtl + 3 * WSZ);

    const int splitg = (M * EMB / 4) / 256;                  // 8192 blocks
    dim3 ggrid(EMB / 128, M / 128);                          // (8, 64)

    split2<<<splitg, 256>>>(query, ahi, alo);
    gemm_ms<<<ggrid, 256, gemm_smem>>>(ahi, alo, wth + 0 * WSZ, wtl + 0 * WSZ, bq, q);
    split2<<<splitg, 256>>>(keys, ahi, alo);
    gemm_ms<<<ggrid, 256, gemm_smem>>>(ahi, alo, wth + 1 * WSZ, wtl + 1 * WSZ, bk, k);
    split2<<<splitg, 256>>>(values, ahi, alo);
    gemm_ms<<<ggrid, 256, gemm_smem>>>(ahi, alo, wth + 2 * WSZ, wtl + 2 * WSZ, bv, v);

    dim3 agrid(S_LEN / BQ, NH, NBATCH);                      // (32, 16, 4)
    attn_kernel<<<agrid, 256, attn_smem>>>(q, k, v, mask, att);

    split2<<<splitg, 256>>>(att, ahi, alo);
    gemm_ms<<<ggrid, 256, gemm_smem>>>(ahi, alo, wth + 3 * WSZ, wtl + 3 * WSZ, bo, out);
}

// round 5
// speedup vs baseline: 1.2863x; 1.0007x over previous
#include <cuda_runtime.h>
#include <cuda_bf16.h>
#include <cstdint>

#define S_LEN 2048
#define NBATCH 4
#define EMB 1024
#define NH 16
#define HD 64

// ---------------------------------------------------------------------------
// Scratch (allocation-free rule: __device__ globals)
// ---------------------------------------------------------------------------
__device__ float g_q[NBATCH * S_LEN * EMB];
__device__ float g_k[NBATCH * S_LEN * EMB];
__device__ float g_v[NBATCH * S_LEN * EMB];
__device__ float g_att[NBATCH * S_LEN * EMB];
__device__ __nv_bfloat16 g_wt_hi[4 * EMB * EMB];   // W^T split high, [4][N][K]
__device__ __nv_bfloat16 g_wt_lo[4 * EMB * EMB];   // W^T split low
__device__ __nv_bfloat16 g_a_hi[NBATCH * S_LEN * EMB];  // activation split high
__device__ __nv_bfloat16 g_a_lo[NBATCH * S_LEN * EMB];  // activation split low

// ---------------------------------------------------------------------------
// Base-ISA PTX helpers (no tcgen05 — harness PTX target is plain sm_103)
// ---------------------------------------------------------------------------
__device__ __forceinline__ uint32_t smem_to_u32(const void* p) {
    uint32_t a;
    asm("{ .reg .u64 t; cvta.to.shared.u64 t, %1; cvt.u32.u64 %0, t; }"
        : "=r"(a) : "l"(p));
    return a;
}

__device__ __forceinline__ void ldsm_x4(uint32_t* r, uint32_t addr) {
    asm volatile("ldmatrix.sync.aligned.m8n8.x4.shared.b16 {%0,%1,%2,%3}, [%4];"
                 : "=r"(r[0]), "=r"(r[1]), "=r"(r[2]), "=r"(r[3]) : "r"(addr));
}

__device__ __forceinline__ void mma_bf16(float* d, const uint32_t* a,
                                         uint32_t b0, uint32_t b1) {
    asm volatile(
        "mma.sync.aligned.m16n8k16.row.col.f32.bf16.bf16.f32 "
        "{%0,%1,%2,%3}, {%4,%5,%6,%7}, {%8,%9}, {%0,%1,%2,%3};"
        : "+f"(d[0]), "+f"(d[1]), "+f"(d[2]), "+f"(d[3])
        : "r"(a[0]), "r"(a[1]), "r"(a[2]), "r"(a[3]), "r"(b0), "r"(b1));
}

__device__ __forceinline__ void cp16(uint32_t s, const void* g) {
    asm volatile("cp.async.cg.shared.global [%0], [%1], 16;" :: "r"(s), "l"(g));
}
__device__ __forceinline__ void cp_commit() {
    asm volatile("cp.async.commit_group;" ::: "memory");
}
template <int N>
__device__ __forceinline__ void cp_wait() {
    asm volatile("cp.async.wait_group %0;" :: "n"(N) : "memory");
}

// ---------------------------------------------------------------------------
// Weight transpose + split: W[K][N] fp32 -> Wt_hi/Wt_lo[N][K] bf16
// ---------------------------------------------------------------------------
__global__ void transpose_split(const float* __restrict__ W,
                                __nv_bfloat16* __restrict__ Th,
                                __nv_bfloat16* __restrict__ Tl)
{
    __shared__ float t[32][33];
    const int tx = threadIdx.x, ty = threadIdx.y;
    const int bx = blockIdx.x * 32, by = blockIdx.y * 32;
#pragma unroll
    for (int j = 0; j < 4; j++)
        t[ty + j * 8][tx] = W[(size_t)(by + ty + j * 8) * EMB + bx + tx];
    __syncthreads();
#pragma unroll
    for (int j = 0; j < 4; j++) {
        float v = t[tx][ty + j * 8];
        __nv_bfloat16 hi = __float2bfloat16_rn(v);
        __nv_bfloat16 lo = __float2bfloat16_rn(v - __bfloat162float(hi));
        const size_t o = (size_t)(bx + ty + j * 8) * EMB + by + tx;
        Th[o] = hi;
        Tl[o] = lo;
    }
}

// ---------------------------------------------------------------------------
// Activation split: X fp32 -> hi/lo bf16 (elementwise)
// ---------------------------------------------------------------------------
union B4 { __nv_bfloat16 b[4]; uint2 u; };

__global__ __launch_bounds__(256)
void split2(const float* __restrict__ X, __nv_bfloat16* __restrict__ H,
            __nv_bfloat16* __restrict__ L)
{
    const int i = blockIdx.x * 256 + threadIdx.x;   // float4 index
    float4 v = ((const float4*)X)[i];
    float f[4] = {v.x, v.y, v.z, v.w};
    B4 h, l;
#pragma unroll
    for (int j = 0; j < 4; j++) {
        h.b[j] = __float2bfloat16_rn(f[j]);
        l.b[j] = __float2bfloat16_rn(f[j] - __bfloat162float(h.b[j]));
    }
    ((uint2*)H)[i] = h.u;
    ((uint2*)L)[i] = l.u;
}

// ---------------------------------------------------------------------------
// mma.sync split-bf16 GEMM: C[M,1024] = A @ W + bias  (fp32-accurate)
// A pre-split hi/lo [M][K] bf16, W pre-transposed+split [N][K] bf16.
// 128x128 block, BK=32, 8 warps (64x32 each), cp.async double buffer.
// ---------------------------------------------------------------------------
#define LDT 40                       // smem row stride (bf16 elems), conflict-free
#define TBY (128 * LDT * 2)          // one tile: 10240 bytes
#define BUFB (4 * TBY)               // Ahi|Alo|Bhi|Blo per buffer

__global__ __launch_bounds__(256, 2)
void gemm_ms(const __nv_bfloat16* __restrict__ Ahi,
             const __nv_bfloat16* __restrict__ Alo,
             const __nv_bfloat16* __restrict__ Bhi,
             const __nv_bfloat16* __restrict__ Blo,
             const float* __restrict__ bias, float* __restrict__ C)
{
    extern __shared__ char smc[];
    const uint32_t sb = smem_to_u32(smc);
    const int tid = threadIdx.x;
    const int wid = tid >> 5, lane = tid & 31;
    const int m0 = blockIdx.y * 128, n0 = blockIdx.x * 128;

    // ---- async load helper data: chunk c in [0,512): row=c>>2, c4=c&3 ----
    const __nv_bfloat16* gp[4] = {Ahi, Alo, Bhi, Blo};
    const int gbase[4] = {m0, m0, n0, n0};

    // ---- ldmatrix lane offset ----
    const int lrow = (lane & 7) + ((lane >> 3) & 1) * 8;
    const int lcol = (lane >> 4) * 8;
    const uint32_t laneoff = (uint32_t)(lrow * (LDT * 2) + lcol * 2);

    const int wm = (wid & 1) * 64;
    const int wn = (wid >> 1) * 32;

    float acc[4][4][4];
#pragma unroll
    for (int i = 0; i < 4; i++)
#pragma unroll
        for (int j = 0; j < 4; j++)
#pragma unroll
            for (int e = 0; e < 4; e++) acc[i][j][e] = 0.0f;

    // ---- prologue: issue buffer 0 (kc = 0) ----
#pragma unroll
    for (int arr = 0; arr < 4; arr++) {
#pragma unroll
        for (int h = 0; h < 2; h++) {
            const int c = tid + h * 256;
            const int row = c >> 2, c4 = c & 3;
            cp16(sb + arr * TBY + row * (LDT * 2) + c4 * 16,
                 gp[arr] + (size_t)(gbase[arr] + row) * EMB + c4 * 8);
        }
    }
    cp_commit();

    const int NKC = EMB / 32;   // 32
    for (int kc = 0; kc < NKC; kc++) {
        const int buf = kc & 1;
        // issue next buffer
        if (kc + 1 < NKC) {
            const uint32_t so = sb + (buf ^ 1) * BUFB;
            const int koff = (kc + 1) * 32;
#pragma unroll
            for (int arr = 0; arr < 4; arr++) {
#pragma unroll
                for (int h = 0; h < 2; h++) {
                    const int c = tid + h * 256;
                    const int row = c >> 2, c4 = c & 3;
                    cp16(so + arr * TBY + row * (LDT * 2) + c4 * 16,
                         gp[arr] + (size_t)(gbase[arr] + row) * EMB + koff + c4 * 8);
                }
            }
            cp_commit();
            cp_wait<1>();
        } else {
            cp_wait<0>();
        }
        __syncthreads();

        const uint32_t tb = sb + buf * BUFB;
#pragma unroll
        for (int ks = 0; ks < 32; ks += 16) {
            uint32_t ah[4][4], al[4][4];
#pragma unroll
            for (int i = 0; i < 4; i++) {
                const uint32_t ao = tb + (wm + i * 16) * (LDT * 2) + ks * 2 + laneoff;
                ldsm_x4(ah[i], ao);
                ldsm_x4(al[i], ao + TBY);
            }
            uint32_t b0[4], b1[4];
            {
                const uint32_t bo = tb + 2 * TBY + wn * (LDT * 2) + ks * 2 + laneoff;
                ldsm_x4(b0, bo);
                ldsm_x4(b1, bo + 16 * (LDT * 2));
            }
            // products: Ahi*Bhi and Alo*Bhi
#pragma unroll
            for (int i = 0; i < 4; i++) {
                mma_bf16(acc[i][0], ah[i], b0[0], b0[2]);
                mma_bf16(acc[i][1], ah[i], b0[1], b0[3]);
                mma_bf16(acc[i][2], ah[i], b1[0], b1[2]);
                mma_bf16(acc[i][3], ah[i], b1[1], b1[3]);
            }
#pragma unroll
            for (int i = 0; i < 4; i++) {
                mma_bf16(acc[i][0], al[i], b0[0], b0[2]);
                mma_bf16(acc[i][1], al[i], b0[1], b0[3]);
                mma_bf16(acc[i][2], al[i], b1[0], b1[2]);
                mma_bf16(acc[i][3], al[i], b1[1], b1[3]);
            }
            // reload B as lo, product Ahi*Blo
            {
                const uint32_t bo = tb + 3 * TBY + wn * (LDT * 2) + ks * 2 + laneoff;
                ldsm_x4(b0, bo);
                ldsm_x4(b1, bo + 16 * (LDT * 2));
            }
#pragma unroll
            for (int i = 0; i < 4; i++) {
                mma_bf16(acc[i][0], ah[i], b0[0], b0[2]);
                mma_bf16(acc[i][1], ah[i], b0[1], b0[3]);
                mma_bf16(acc[i][2], ah[i], b1[0], b1[2]);
                mma_bf16(acc[i][3], ah[i], b1[1], b1[3]);
            }
        }
        __syncthreads();
    }

    // ---- epilogue: bias + store ----
#pragma unroll
    for (int i = 0; i < 4; i++) {
        const int r = m0 + wm + i * 16 + (lane >> 2);
#pragma unroll
        for (int j = 0; j < 4; j++) {
            const int c = n0 + wn + j * 8 + (lane & 3) * 2;
            const float2 bv = *(const float2*)(bias + c);
            float2 o0, o1;
            o0.x = acc[i][j][0] + bv.x;
            o0.y = acc[i][j][1] + bv.y;
            o1.x = acc[i][j][2] + bv.x;
            o1.y = acc[i][j][3] + bv.y;
            *(float2*)(C + (size_t)r * EMB + c) = o0;
            *(float2*)(C + (size_t)(r + 8) * EMB + c) = o1;
        }
    }
}

// ---------------------------------------------------------------------------
// Flash attention, fp32 (unchanged — proven correct, round-2)
// ---------------------------------------------------------------------------
#define BQ 64
#define BKT 64
#define DP 68

__global__ __launch_bounds__(256)
void attn_kernel(const float* __restrict__ Q, const float* __restrict__ Kt,
                 const float* __restrict__ V, const int* __restrict__ mask,
                 float* __restrict__ Out)
{
    extern __shared__ float sm[];
    float (*Qs)[DP]  = (float(*)[DP])sm;
    float (*KPs)[DP] = (float(*)[DP])(sm + HD * DP);
    float (*Vs)[DP]  = (float(*)[DP])(sm + 2 * HD * DP);

    const int tid = threadIdx.x;
    const int tx = tid & 15;
    const int ty = tid >> 4;
    const int qb = blockIdx.x;
    const int h  = blockIdx.y;
    const int n  = blockIdx.z;

    const int q0 = qb * BQ;
    const size_t base = ((size_t)n * S_LEN) * EMB + (size_t)h * HD;

    {
        const int tok = tid >> 2;
        const int d0 = (tid & 3) * 16;
        const float* src = Q + base + (size_t)(q0 + tok) * EMB + d0;
#pragma unroll
        for (int u = 0; u < 4; u++) {
            float4 v = *(const float4*)(src + u * 4);
            Qs[d0 + u * 4 + 0][tok] = v.x * 0.03125f;
            Qs[d0 + u * 4 + 1][tok] = v.y * 0.03125f;
            Qs[d0 + u * 4 + 2][tok] = v.z * 0.03125f;
            Qs[d0 + u * 4 + 3][tok] = v.w * 0.03125f;
        }
    }

    float o[4][4] = {};
    float mrow[4], lrow[4];
#pragma unroll
    for (int i = 0; i < 4; i++) { mrow[i] = -3.0e38f; lrow[i] = 0.0f; }

    for (int kt = 0; kt < S_LEN / BKT; kt++) {
        const int k0 = kt * BKT;
        __syncthreads();
        {
            const int tok = tid >> 2;
            const int d0 = (tid & 3) * 16;
            const float* ksrc = Kt + base + (size_t)(k0 + tok) * EMB + d0;
            const float* vsrc = V  + base + (size_t)(k0 + tok) * EMB + d0;
#pragma unroll
            for (int u = 0; u < 4; u++) {
                float4 kv = *(const float4*)(ksrc + u * 4);
                KPs[d0 + u * 4 + 0][tok] = kv.x;
                KPs[d0 + u * 4 + 1][tok] = kv.y;
                KPs[d0 + u * 4 + 2][tok] = kv.z;
                KPs[d0 + u * 4 + 3][tok] = kv.w;
                *(float4*)&Vs[tok][d0 + u * 4] = *(const float4*)(vsrc + u * 4);
            }
        }
        __syncthreads();

        float s[4][4] = {};
#pragma unroll 8
        for (int d = 0; d < HD; d++) {
            float4 a = *(const float4*)&Qs[d][ty * 4];
            float4 b = *(const float4*)&KPs[d][tx * 4];
            float av[4] = {a.x, a.y, a.z, a.w};
            float bv[4] = {b.x, b.y, b.z, b.w};
#pragma unroll
            for (int i = 0; i < 4; i++)
#pragma unroll
                for (int j = 0; j < 4; j++)
                    s[i][j] += av[i] * bv[j];
        }

        {
            const int* mp = mask + n * S_LEN + k0 + tx * 4;
#pragma unroll
            for (int j = 0; j < 4; j++) {
                if (mp[j] == 0) {
                    s[0][j] = -1e20f; s[1][j] = -1e20f;
                    s[2][j] = -1e20f; s[3][j] = -1e20f;
                }
            }
        }

        float p[4][4];
#pragma unroll
        for (int i = 0; i < 4; i++) {
            float rm = fmaxf(fmaxf(s[i][0], s[i][1]), fmaxf(s[i][2], s[i][3]));
#pragma unroll
            for (int off = 8; off >= 1; off >>= 1)
                rm = fmaxf(rm, __shfl_xor_sync(0xffffffffu, rm, off, 16));
            const float mnew = fmaxf(mrow[i], rm);
            const float corr = __expf(mrow[i] - mnew);
            mrow[i] = mnew;
            float ls = 0.0f;
#pragma unroll
            for (int j = 0; j < 4; j++) {
                p[i][j] = __expf(s[i][j] - mnew);
                ls += p[i][j];
            }
#pragma unroll
            for (int off = 8; off >= 1; off >>= 1)
                ls += __shfl_xor_sync(0xffffffffu, ls, off, 16);
            lrow[i] = lrow[i] * corr + ls;
#pragma unroll
            for (int j = 0; j < 4; j++) o[i][j] *= corr;
        }

        __syncthreads();
#pragma unroll
        for (int i = 0; i < 4; i++)
#pragma unroll
            for (int j = 0; j < 4; j++)
                KPs[ty * 4 + i][tx * 4 + j] = p[i][j];
        __syncthreads();

#pragma unroll 8
        for (int k = 0; k < BKT; k++) {
            float4 vv = *(const float4*)&Vs[k][tx * 4];
#pragma unroll
            for (int i = 0; i < 4; i++) {
                const float pv = KPs[ty * 4 + i][k];
                o[i][0] += pv * vv.x;
                o[i][1] += pv * vv.y;
                o[i][2] += pv * vv.z;
                o[i][3] += pv * vv.w;
            }
        }
    }

#pragma unroll
    for (int i = 0; i < 4; i++) {
        const float inv = 1.0f / lrow[i];
        float4 ov = make_float4(o[i][0] * inv, o[i][1] * inv,
                                o[i][2] * inv, o[i][3] * inv);
        *(float4*)(Out + base + (size_t)(q0 + ty * 4 + i) * EMB + tx * 4) = ov;
    }
}

// ---------------------------------------------------------------------------
extern "C" void kernel_launch(void* const* d_in, const int* in_sizes, int n_in,
                              void* d_out, int out_size)
{
    const float* values = (const float*)d_in[0];
    const float* keys   = (const float*)d_in[1];
    const float* query  = (const float*)d_in[2];
    const int*   mask   = (const int*)  d_in[3];
    const float* Wv = (const float*)d_in[4];
    const float* bv = (const float*)d_in[5];
    const float* Wk = (const float*)d_in[6];
    const float* bk = (const float*)d_in[7];
    const float* Wq = (const float*)d_in[8];
    const float* bq = (const float*)d_in[9];
    const float* Wo = (const float*)d_in[10];
    const float* bo = (const float*)d_in[11];
    float* out = (float*)d_out;

    float *q, *k, *v, *att;
    __nv_bfloat16 *wth, *wtl, *ahi, *alo;
    cudaGetSymbolAddress((void**)&q,   g_q);
    cudaGetSymbolAddress((void**)&k,   g_k);
    cudaGetSymbolAddress((void**)&v,   g_v);
    cudaGetSymbolAddress((void**)&att, g_att);
    cudaGetSymbolAddress((void**)&wth, g_wt_hi);
    cudaGetSymbolAddress((void**)&wtl, g_wt_lo);
    cudaGetSymbolAddress((void**)&ahi, g_a_hi);
    cudaGetSymbolAddress((void**)&alo, g_a_lo);

    const int gemm_smem = 2 * BUFB;                          // 81920 B
    cudaFuncSetAttribute(gemm_ms,
                         cudaFuncAttributeMaxDynamicSharedMemorySize, gemm_smem);
    const int attn_smem = 3 * HD * DP * (int)sizeof(float);  // 52224 B
    cudaFuncSetAttribute(attn_kernel,
                         cudaFuncAttributeMaxDynamicSharedMemorySize, attn_smem);

    const size_t WSZ = (size_t)EMB * EMB;
    const int M = NBATCH * S_LEN;                            // 8192
    dim3 tgrid(32, 32), tblk(32, 8);
    transpose_split<<<tgrid, tblk>>>(Wq, wth + 0 * WSZ, wtl + 0 * WSZ);
    transpose_split<<<tgrid, tblk>>>(Wk, wth + 1 * WSZ, wtl + 1 * WSZ);
    transpose_split<<<tgrid, tblk>>>(Wv, wth + 2 * WSZ, wtl + 2 * WSZ);
    transpose_split<<<tgrid, tblk>>>(Wo, wth + 3 * WSZ, wtl + 3 * WSZ);

    const int splitg = (M * EMB / 4) / 256;                  // 8192 blocks
    dim3 ggrid(EMB / 128, M / 128);                          // (8, 64)

    split2<<<splitg, 256>>>(query, ahi, alo);
    gemm_ms<<<ggrid, 256, gemm_smem>>>(ahi, alo, wth + 0 * WSZ, wtl + 0 * WSZ, bq, q);
    split2<<<splitg, 256>>>(keys, ahi, alo);
    gemm_ms<<<ggrid, 256, gemm_smem>>>(ahi, alo, wth + 1 * WSZ, wtl + 1 * WSZ, bk, k);
    split2<<<splitg, 256>>>(values, ahi, alo);
    gemm_ms<<<ggrid, 256, gemm_smem>>>(ahi, alo, wth + 2 * WSZ, wtl + 2 * WSZ, bv, v);

    dim3 agrid(S_LEN / BQ, NH, NBATCH);                      // (32, 16, 4)
    attn_kernel<<<agrid, 256, attn_smem>>>(q, k, v, mask, att);

    split2<<<splitg, 256>>>(att, ahi, alo);
    gemm_ms<<<ggrid, 256, gemm_smem>>>(ahi, alo, wth + 3 * WSZ, wtl + 3 * WSZ, bo, out);
}